// round 4
// baseline (speedup 1.0000x reference)
#include <cuda_runtime.h>
#include <cuda_bf16.h>

// Problem constants (fixed by setup_inputs)
#define BSZ   4
#define CCH   256
#define HWSZ  1024      // 32*32
#define NQ    300
#define NCLS  80
#define TOPK  150
#define NWORK 1024      // worker blocks (4096 rows / 4 rows per block)
#define GRID  (NWORK + BSZ)

__device__ int d_src[BSZ][HWSZ];
__device__ int d_objnum[BSZ];
__device__ int d_done;     // static-init 0; self-reset each run
__device__ int d_arrive;   // static-init 0; self-reset each run

// ---------------------------------------------------------------------------
// One fused kernel. Blocks 0..3: per-batch prep (mask + compaction), publish
// with release. Blocks 4..1027: spin (bounded, nanosleep backoff), then write
// 4 output rows each: zero-fill via STG.128 or scalar gather for data rows.
// out layout: [sparse_key (1024,4,256)][sparse_key_pos (1024,4,256)] fp32
// ---------------------------------------------------------------------------
__global__ void __launch_bounds__(256, 6)
fused_kernel(const float* __restrict__ x,            // (4,256,32,32)
             const float* __restrict__ pos,          // (4,256,32,32)
             const unsigned char* __restrict__ padmask, // (4,1024)
             const float* __restrict__ coord,        // (4,300,4)
             const float* __restrict__ cls_logits,   // (4,300,80)
             const int*   __restrict__ sizes,        // (4,2)
             float* __restrict__ out)
{
    const int bid = blockIdx.x;
    const int t   = threadIdx.x;

    if (bid < BSZ) {
        // ================= PREP (batch b = bid, 256 threads) ==============
        __shared__ float    svals[NQ];
        __shared__ unsigned rowmask[32];
        __shared__ int      wsum8[8];
        __shared__ int      sbase;

        const int b    = bid;
        const int lane = t & 31;
        const int wid  = t >> 5;

        if (t < 32) rowmask[t] = 0u;
        if (t == 0) sbase = 0;

        // --- 1) per-query class max (rows t and t+256) --------------------
        for (int row = t; row < NQ; row += 256) {
            const float4* r = (const float4*)(cls_logits + (size_t)(b * NQ + row) * NCLS);
            float4 v = r[0];
            float m = fmaxf(fmaxf(v.x, v.y), fmaxf(v.z, v.w));
            #pragma unroll
            for (int k = 1; k < NCLS / 4; k++) {
                v = r[k];
                m = fmaxf(m, fmaxf(fmaxf(v.x, v.y), fmaxf(v.z, v.w)));
            }
            svals[row] = m;
        }
        __syncthreads();

        // --- 2) top-150 set via pairwise rank; rasterize boxes ------------
        const float ts0 = (float)sizes[b * 2 + 0];
        const float ts1 = (float)sizes[b * 2 + 1];
        {
            const int  r1   = t;              // always < 300
            const int  r2   = t + 256;
            const bool has2 = (r2 < NQ);
            const float v1 = svals[r1];
            const float v2 = has2 ? svals[r2] : 0.0f;
            int rank1 = 0, rank2 = 0;
            #pragma unroll 4
            for (int j = 0; j < NQ; j++) {
                const float vj = svals[j];
                rank1 += (vj > v1) || (vj == v1 && j < r1);
                rank2 += (vj > v2) || (vj == v2 && j < r2);
            }
            #pragma unroll
            for (int which = 0; which < 2; which++) {
                const int  row = which ? r2 : r1;
                const int  rk  = which ? rank2 : rank1;
                const bool ok  = which ? (has2 && rank2 < TOPK) : (rank1 < TOPK);
                (void)rk;
                if (ok) {
                    const float* bx = coord + (size_t)(b * NQ + row) * 4;
                    float cx = bx[0], cy = bx[1], bw = bx[2], bh = bx[3];
                    // one rounding per op (matches XLA); *0.0625f is exact
                    float x1 = ts0 * (cx - 0.5f * bw);
                    float y1 = ts1 * (cy - 0.5f * bh);
                    float x2 = ts0 * (cx + 0.5f * bw);
                    float y2 = ts1 * (cy + 0.5f * bh);
                    // j*16 > x1 <=> j > x1/16 (exact); j*16 < x2 <=> j < x2/16
                    int jlo = (int)floorf(x1 * 0.0625f) + 1;
                    int jhi = (int)ceilf (x2 * 0.0625f) - 1;
                    int ilo = (int)floorf(y1 * 0.0625f) + 1;
                    int ihi = (int)ceilf (y2 * 0.0625f) - 1;
                    jlo = max(jlo, 0);  jhi = min(jhi, 31);
                    ilo = max(ilo, 0);  ihi = min(ihi, 31);
                    if (jlo <= jhi && ilo <= ihi) {
                        unsigned jmask = ((jhi == 31) ? 0xFFFFFFFFu : ((1u << (jhi + 1)) - 1u))
                                       & ~((1u << jlo) - 1u);
                        for (int i = ilo; i <= ihi; i++) atomicOr(&rowmask[i], jmask);
                    }
                }
            }
        }
        __syncthreads();

        // --- 3) compaction: 4 rounds of 256-point ballot scan -------------
        #pragma unroll
        for (int rnd = 0; rnd < 4; rnd++) {
            const int p = rnd * 256 + t;
            const int i = p >> 5, j = p & 31;
            const int inbox = (rowmask[i] >> j) & 1u;
            const int om = (!inbox) | (padmask[b * HWSZ + p] != 0);

            unsigned bal = __ballot_sync(0xffffffffu, om);
            if (lane == 0) wsum8[wid] = __popc(bal);
            __syncthreads();
            if (t == 0) {
                int acc = sbase;
                #pragma unroll
                for (int k = 0; k < 8; k++) { int v = wsum8[k]; wsum8[k] = acc; acc += v; }
                sbase = acc;
            }
            __syncthreads();
            const int off = wsum8[wid] + __popc(bal & ((1u << lane) - 1u));
            if (om) d_src[b][off] = p;
            __syncthreads();
        }

        // --- 4) publish (release) -----------------------------------------
        if (t == 0) {
            d_objnum[b] = sbase;
            __threadfence();
            atomicAdd(&d_done, 1);
        }
        return;
    }

    // ==================== WORKER (4 output rows per block) ================
    const int wb = bid - BSZ;

    if (t == 0) {
        long it = 0;
        while (atomicAdd(&d_done, 0) < BSZ) {
            if (++it > (1L << 22)) break;   // safety bound: no hang
            __nanosleep(128);
        }
    }
    __syncthreads();
    __threadfence();                        // acquire side

    const int grp = t >> 6;                 // 0..3 -> which of my 4 rows
    const int f4  = t & 63;                 // float4 index within the row
    const int row = wb * 4 + grp;           // linear row id = p*4 + b
    const int p   = row >> 2;
    const int b   = row & 3;

    const size_t out2 = (size_t)HWSZ * BSZ * CCH;
    const size_t o    = (size_t)row * CCH + (size_t)f4 * 4;

    if (p < d_objnum[b]) {
        const int s = d_src[b][p];
        float4 k4, p4;
        const size_t base = ((size_t)(b * CCH + f4 * 4) << 10) + s;
        k4.x = __ldg(x + base);
        k4.y = __ldg(x + base + 1024);
        k4.z = __ldg(x + base + 2048);
        k4.w = __ldg(x + base + 3072);
        p4.x = __ldg(pos + base);
        p4.y = __ldg(pos + base + 1024);
        p4.z = __ldg(pos + base + 2048);
        p4.w = __ldg(pos + base + 3072);
        *(float4*)(out + o)        = k4;
        *(float4*)(out + out2 + o) = p4;
    } else {
        const float4 z = make_float4(0.f, 0.f, 0.f, 0.f);
        *(float4*)(out + o)        = z;
        *(float4*)(out + out2 + o) = z;
    }

    // ---- self-resetting barrier (keeps replays deterministic) -----------
    __syncthreads();
    if (t == 0) {
        const int old = atomicAdd(&d_arrive, 1);
        if (old == NWORK - 1) {             // last worker: everyone passed the spin
            atomicExch(&d_done, 0);
            atomicExch(&d_arrive, 0);
        }
    }
}

// ---------------------------------------------------------------------------
extern "C" void kernel_launch(void* const* d_in, const int* in_sizes, int n_in,
                              void* d_out, int out_size)
{
    const float* x        = (const float*)d_in[0];  // (4,256,32,32)
    const float* pos      = (const float*)d_in[1];  // (4,256,32,32)
    const unsigned char* msk = (const unsigned char*)d_in[2]; // (4,32,32)
    const float* coord    = (const float*)d_in[3];  // (4,300,4)
    const float* clsl     = (const float*)d_in[4];  // (4,300,80)
    const int*   sizes    = (const int*)d_in[5];    // (4,2)
    float* out = (float*)d_out;

    fused_kernel<<<GRID, 256>>>(x, pos, msk, coord, clsl, sizes, out);
}

// round 5
// speedup vs baseline: 1.1969x; 1.1969x over previous
#include <cuda_runtime.h>
#include <cuda_bf16.h>

// Problem constants (fixed by setup_inputs)
#define BSZ   4
#define CCH   256
#define HWSZ  1024      // 32*32
#define NQ    300
#define NCLS  80
#define TOPK  150
// batched_h = batched_w = 512, grid step = 16

__device__ int d_src[BSZ][HWSZ];
__device__ int d_objnum[BSZ];

// monotone float->uint map: preserves >, ==, < for all non-NaN floats
__device__ __forceinline__ unsigned fmap(float f) {
    unsigned u = __float_as_uint(f);
    return (u & 0x80000000u) ? ~u : (u | 0x80000000u);
}

// ---------------------------------------------------------------------------
// Kernel 1: control.  <<<4, 1024>>>
// 3 threads/row for class-max (batched loads, atomicMax) and rank (split 100
// iters each, atomicAdd).  Then box raster -> 32-word bitmask -> ballot scan.
// ---------------------------------------------------------------------------
__global__ void __launch_bounds__(1024, 1)
prep_kernel(const float* __restrict__ coord,       // (BSZ,NQ,4)
            const float* __restrict__ cls_logits,  // (BSZ,NQ,NCLS)
            const int*   __restrict__ sizes,       // (BSZ,2)
            const unsigned char* __restrict__ padmask) // (BSZ,HWSZ)
{
    __shared__ unsigned smax[NQ];     // mapped max bits
    __shared__ int      srank[NQ];
    __shared__ unsigned rowmask[32];
    __shared__ int      wsum[32];

    const int b    = blockIdx.x;
    const int tid  = threadIdx.x;
    const int lane = tid & 31;
    const int wid  = tid >> 5;

    if (tid < NQ)  { smax[tid] = 0u; srank[tid] = 0; }
    if (tid < 32)  rowmask[tid] = 0u;
    __syncthreads();

    const int  row  = tid / 3;          // 0..341
    const int  part = tid - row * 3;    // 0..2
    const bool act  = (tid < 3 * NQ);   // 900 active

    // --- 1) class max: each of 3 threads loads a 7-float4 chunk (batched) --
    if (act) {
        const float4* r = (const float4*)(cls_logits + (size_t)(b * NQ + row) * NCLS);
        const int k0 = part * 7;        // chunks 0..6, 7..13, 14..19
        float m = -1e30f;
        #pragma unroll
        for (int kk = 0; kk < 7; kk++) {
            const int k = k0 + kk;
            if (k < NCLS / 4) {
                float4 v = r[k];
                m = fmaxf(m, fmaxf(fmaxf(v.x, v.y), fmaxf(v.z, v.w)));
            }
        }
        atomicMax(&smax[row], fmap(m));
    }
    __syncthreads();

    // --- 2) rank: 3x100 comparisons per row, combined via atomicAdd -------
    if (act) {
        const unsigned vi = smax[row];
        const int j0 = part * 100;
        int cnt = 0;
        #pragma unroll 4
        for (int j = j0; j < j0 + 100; j++) {
            const unsigned vj = smax[j];
            cnt += (vj > vi) || (vj == vi && j < row);
        }
        atomicAdd(&srank[row], cnt);
    }
    __syncthreads();

    // --- 3) top-150 rows -> scaled boxes -> raster into rowmask ------------
    const float ts0 = (float)sizes[b * 2 + 0];
    const float ts1 = (float)sizes[b * 2 + 1];
    if (tid < NQ && srank[tid] < TOPK) {
        const float* bx = coord + (size_t)(b * NQ + tid) * 4;
        float cx = bx[0], cy = bx[1], bw = bx[2], bh = bx[3];
        // one rounding per op (matches XLA); *0.0625f is exact (exp shift)
        float x1 = ts0 * (cx - 0.5f * bw);
        float y1 = ts1 * (cy - 0.5f * bh);
        float x2 = ts0 * (cx + 0.5f * bw);
        float y2 = ts1 * (cy + 0.5f * bh);
        // j*16 > x1 <=> j > x1/16 (exact);  j*16 < x2 <=> j < x2/16
        int jlo = (int)floorf(x1 * 0.0625f) + 1;
        int jhi = (int)ceilf (x2 * 0.0625f) - 1;
        int ilo = (int)floorf(y1 * 0.0625f) + 1;
        int ihi = (int)ceilf (y2 * 0.0625f) - 1;
        jlo = max(jlo, 0);  jhi = min(jhi, 31);
        ilo = max(ilo, 0);  ihi = min(ihi, 31);
        if (jlo <= jhi && ilo <= ihi) {
            unsigned jmask = ((jhi == 31) ? 0xFFFFFFFFu : ((1u << (jhi + 1)) - 1u))
                           & ~((1u << jlo) - 1u);
            for (int i = ilo; i <= ihi; i++) atomicOr(&rowmask[i], jmask);
        }
    }
    __syncthreads();

    // --- 4) per-point mask + ballot compaction (ascending index order) ----
    const int gi = tid >> 5, gj = tid & 31;
    const int inbox = (rowmask[gi] >> gj) & 1u;
    const int om = (!inbox) | (padmask[b * HWSZ + tid] != 0);

    unsigned bal = __ballot_sync(0xffffffffu, om);
    if (lane == 0) wsum[wid] = __popc(bal);
    __syncthreads();
    if (wid == 0) {
        int v = wsum[lane];
        #pragma unroll
        for (int o = 1; o < 32; o <<= 1) {
            int tshf = __shfl_up_sync(0xffffffffu, v, o);
            if (lane >= o) v += tshf;
        }
        wsum[lane] = v;   // inclusive
    }
    __syncthreads();
    const int warp_off = wid ? wsum[wid - 1] : 0;
    const int pre = __popc(bal & ((1u << lane) - 1u));
    if (om) d_src[b][warp_off + pre] = tid;
    if (tid == 1023) d_objnum[b] = wsum[31];
}

// ---------------------------------------------------------------------------
// Kernel 2: gather/zero-fill, flat float4 indexing.  <<<256, 256>>>
// q indexes float4s of the first output array (262144 total). Each thread
// handles 4 q's; consecutive threads -> consecutive addresses (coalesced).
// out: [sparse_key (1024,4,256)][sparse_key_pos (1024,4,256)] fp32
// ---------------------------------------------------------------------------
#define NQ4    (HWSZ * BSZ * CCH / 4)    // 262144 float4 per array
#define GTHR   65536                     // 256 blocks * 256 threads
#define GITER  (NQ4 / GTHR)              // 4

__global__ void __launch_bounds__(256, 8)
gather_kernel(const float* __restrict__ x,
              const float* __restrict__ pos,
              float* __restrict__ out)
{
    const int tg = blockIdx.x * 256 + threadIdx.x;

    // cache objnums (tiny, L1-resident)
    int on0 = d_objnum[0], on1 = d_objnum[1];
    int on2 = d_objnum[2], on3 = d_objnum[3];

    float4* __restrict__ o0 = (float4*)out;
    float4* __restrict__ o1 = (float4*)out + NQ4;
    const float4 z = make_float4(0.f, 0.f, 0.f, 0.f);

    #pragma unroll
    for (int i = 0; i < GITER; i++) {
        const int q   = i * GTHR + tg;
        const int f4  = q & 63;          // float4 within row (c = f4*4)
        const int rw  = q >> 6;          // row = p*4 + b
        const int p   = rw >> 2;
        const int b   = rw & 3;
        const int on  = (b == 0) ? on0 : (b == 1) ? on1 : (b == 2) ? on2 : on3;

        if (p < on) {
            const int s = d_src[b][p];
            const size_t base = ((size_t)(b * CCH + f4 * 4) << 10) + s;
            float4 k4, p4;
            k4.x = __ldg(x + base);
            k4.y = __ldg(x + base + 1024);
            k4.z = __ldg(x + base + 2048);
            k4.w = __ldg(x + base + 3072);
            p4.x = __ldg(pos + base);
            p4.y = __ldg(pos + base + 1024);
            p4.z = __ldg(pos + base + 2048);
            p4.w = __ldg(pos + base + 3072);
            o0[q] = k4;
            o1[q] = p4;
        } else {
            o0[q] = z;
            o1[q] = z;
        }
    }
}

// ---------------------------------------------------------------------------
extern "C" void kernel_launch(void* const* d_in, const int* in_sizes, int n_in,
                              void* d_out, int out_size)
{
    const float* x        = (const float*)d_in[0];  // (4,256,32,32)
    const float* pos      = (const float*)d_in[1];  // (4,256,32,32)
    const unsigned char* msk = (const unsigned char*)d_in[2]; // (4,32,32)
    const float* coord    = (const float*)d_in[3];  // (4,300,4)
    const float* clsl     = (const float*)d_in[4];  // (4,300,80)
    const int*   sizes    = (const int*)d_in[5];    // (4,2)
    float* out = (float*)d_out;

    prep_kernel<<<BSZ, 1024>>>(coord, clsl, sizes, msk);
    gather_kernel<<<256, 256>>>(x, pos, out);
}